// round 15
// baseline (speedup 1.0000x reference)
#include <cuda_runtime.h>
#include <cuda_fp16.h>
#include <cstdint>
#include <math.h>

// Problem dims (fixed)
#define Bn 8
#define Tn 1024
#define Cn 1024
#define NHh 16
#define HDd 64
#define FFf 4096
#define MROWS (Bn*Tn)   // 8192

// Weight offsets inside the packed transposed-weight buffer (elements)
#define OFF_QKV 0
#define OFF_PROJ (3*Cn*Cn)
#define OFF_FC   (OFF_PROJ + Cn*Cn)
#define OFF_FC2  (OFF_FC + (size_t)FFf*Cn)
#define WSUM     (OFF_FC2 + (size_t)Cn*FFf)

// ---------------- scratch (static device globals; no allocation) -------------
static __device__ __align__(16) __half  g_qkvh[(size_t)MROWS*3*Cn]; // 48 MB
static __device__ __align__(16) float   g_x1 [(size_t)MROWS*Cn];    // 32 MB
static __device__ __align__(16) __half  g_ah [(size_t)MROWS*Cn];    // LN out fp16
static __device__ __align__(16) __half  g_yh [(size_t)MROWS*Cn];    // attn out fp16
static __device__ __align__(16) __half  g_ffh[(size_t)MROWS*FFf];   // relu(fc) fp16
static __device__ __align__(16) __half  g_wh [WSUM];                // W^T fp16

// ---------------- small helpers ------------------------------------------------
__device__ __forceinline__ uint32_t smem_u32(const void* p) {
    uint32_t a;
    asm("{ .reg .u64 t; cvta.to.shared.u64 t, %1; cvt.u32.u64 %0, t; }" : "=r"(a) : "l"(p));
    return a;
}
__device__ __forceinline__ void cp16(uint32_t dst, const void* src) {
    asm volatile("cp.async.cg.shared.global [%0], [%1], 16;" :: "r"(dst), "l"(src) : "memory");
}
__device__ __forceinline__ uint32_t pkh2(float a, float b) {
    __half2 t = __floats2half2_rn(a, b);
    return *reinterpret_cast<uint32_t*>(&t);
}
__device__ __forceinline__ void ldm_x4(uint32_t* r, uint32_t addr) {
    asm volatile("ldmatrix.sync.aligned.m8n8.x4.shared.b16 {%0,%1,%2,%3}, [%4];"
                 : "=r"(r[0]), "=r"(r[1]), "=r"(r[2]), "=r"(r[3]) : "r"(addr));
}
__device__ __forceinline__ void ldm_x2(uint32_t* r, uint32_t addr) {
    asm volatile("ldmatrix.sync.aligned.m8n8.x2.shared.b16 {%0,%1}, [%2];"
                 : "=r"(r[0]), "=r"(r[1]) : "r"(addr));
}
__device__ __forceinline__ void ldm_x2t(uint32_t* r, uint32_t addr) {
    asm volatile("ldmatrix.sync.aligned.m8n8.x2.trans.shared.b16 {%0,%1}, [%2];"
                 : "=r"(r[0]), "=r"(r[1]) : "r"(addr));
}
__device__ __forceinline__ void mma16816(float* c, const uint32_t* a, const uint32_t* b) {
    asm volatile(
        "mma.sync.aligned.m16n8k16.row.col.f32.f16.f16.f32 "
        "{%0,%1,%2,%3}, {%4,%5,%6,%7}, {%8,%9}, {%0,%1,%2,%3};"
        : "+f"(c[0]), "+f"(c[1]), "+f"(c[2]), "+f"(c[3])
        : "r"(a[0]), "r"(a[1]), "r"(a[2]), "r"(a[3]), "r"(b[0]), "r"(b[1]));
}

// ---------------- LayerNorm -> fp16 --------------------------------------------
__global__ __launch_bounds__(256)
void ln_h_kernel(const float* __restrict__ x, const float* __restrict__ gamma,
                 const float* __restrict__ beta, __half* __restrict__ oh)
{
    const int row = blockIdx.x;
    const float4* xr = reinterpret_cast<const float4*>(x + (size_t)row * Cn);
    float4 v = xr[threadIdx.x];
    float s  = v.x + v.y + v.z + v.w;
    float ss = v.x*v.x + v.y*v.y + v.z*v.z + v.w*v.w;
    #pragma unroll
    for (int o = 16; o > 0; o >>= 1) {
        s  += __shfl_xor_sync(0xffffffffu, s,  o);
        ss += __shfl_xor_sync(0xffffffffu, ss, o);
    }
    __shared__ float rs[8], rss[8];
    const int w = threadIdx.x >> 5;
    if ((threadIdx.x & 31) == 0) { rs[w] = s; rss[w] = ss; }
    __syncthreads();
    if (threadIdx.x < 32) {
        float ts  = (threadIdx.x < 8) ? rs[threadIdx.x]  : 0.f;
        float tss = (threadIdx.x < 8) ? rss[threadIdx.x] : 0.f;
        #pragma unroll
        for (int o = 4; o > 0; o >>= 1) {
            ts  += __shfl_xor_sync(0xffffffffu, ts,  o);
            tss += __shfl_xor_sync(0xffffffffu, tss, o);
        }
        if (threadIdx.x == 0) {
            float mean = ts * (1.0f/Cn);
            float var  = tss * (1.0f/Cn) - mean*mean;
            rs[0]  = mean;
            rss[0] = rsqrtf(var + 1e-5f);
        }
    }
    __syncthreads();
    const float mean = rs[0], rstd = rss[0];
    const float4 g4 = reinterpret_cast<const float4*>(gamma)[threadIdx.x];
    const float4 b4 = reinterpret_cast<const float4*>(beta )[threadIdx.x];
    uint2 h;
    h.x = pkh2((v.x - mean)*rstd*g4.x + b4.x, (v.y - mean)*rstd*g4.y + b4.y);
    h.y = pkh2((v.z - mean)*rstd*g4.z + b4.z, (v.w - mean)*rstd*g4.w + b4.w);
    *reinterpret_cast<uint2*>(oh + (size_t)row*Cn + threadIdx.x*4) = h;
}

// ---------------- weight transpose: W[K,N] -> Wt[N,K] fp16 ---------------------
__global__ __launch_bounds__(256)
void wt_h_kernel(const float* __restrict__ W, __half* __restrict__ wh, int K, int N)
{
    __shared__ float tile[32][33];
    const int n0 = blockIdx.x * 32, k0 = blockIdx.y * 32;
    const int tx = threadIdx.x & 31, ty = threadIdx.x >> 5;   // 32 x 8
    #pragma unroll
    for (int yy = ty; yy < 32; yy += 8)
        tile[yy][tx] = W[(size_t)(k0 + yy)*N + n0 + tx];
    __syncthreads();
    #pragma unroll
    for (int yy = ty; yy < 32; yy += 8)
        wh[(size_t)(n0 + yy)*K + k0 + tx] = __float2half_rn(tile[tx][yy]);
}

// ---------------- mma.sync fp16 GEMM (8 warps, 256x128 block, 2-stage) ---------
// C = A @ B^T : A [M,K] fp16 row-major, B rows = Wt[N,K] fp16.
// Block 256x128, BK=32, 8 warps (4x2), warp tile 64x64.
// Rows 64B; 16B chunk swizzle: phys = ch ^ ((row>>1)&3). Conflict-free ldmatrix.
// Stage = A(16KB) + B(8KB) = 24KB; 2 stages = 48KB static.
// MODE 0: outH = C+bias (fp16) ; MODE 1: outF = C+bias+resid (fp32) ;
// MODE 2: relu(C+bias) -> fp16
#define ATILE 16384                     // 256 rows * 64 B
#define BTILE 8192                      // 128 rows * 64 B
#define GSTG  (ATILE + BTILE)           // 24576 B

template<int MODE>
__global__ __launch_bounds__(256, 1)
void tc_gemm(const __half* __restrict__ Ah, const __half* __restrict__ Bh,
             const float* __restrict__ bias, const float* __restrict__ resid,
             float* __restrict__ outF, __half* __restrict__ outH,
             int M, int N, int K)
{
    __shared__ __align__(16) char smem[2*GSTG];   // 49152 B
    const uint32_t tb = smem_u32(smem);
    const int tid = threadIdx.x;
    const int wid = tid >> 5, lane = tid & 31;
    const int bm = blockIdx.y << 8, bn = blockIdx.x << 7;
    const int wm = (wid >> 1) * 64;      // warp M offset (0/64/128/192)
    const int wn = (wid & 1) * 64;       // warp N offset (0/64)

    float acc[4][8][4];
    #pragma unroll
    for (int i = 0; i < 4; ++i)
        #pragma unroll
        for (int j = 0; j < 8; ++j)
            #pragma unroll
            for (int q = 0; q < 4; ++q) acc[i][j][q] = 0.f;

    // loads per stage: A 1024 units (4/thr), B 512 units (2/thr)
    auto issue_loads = [&](int c, int s) {
        const uint32_t st = tb + s*GSTG;
        const int kc = c << 5;
        #pragma unroll
        for (int i = 0; i < 4; ++i) {
            const int u = tid + i*256;
            const int row = u >> 2, ch = u & 3;
            const uint32_t so = (uint32_t)(row*64 + ((ch ^ ((row>>1)&3)))*16);
            cp16(st + so, Ah + (size_t)(bm + row)*K + kc + ch*8);
        }
        #pragma unroll
        for (int i = 0; i < 2; ++i) {
            const int u = tid + i*256;
            const int row = u >> 2, ch = u & 3;
            const uint32_t so = (uint32_t)(row*64 + ((ch ^ ((row>>1)&3)))*16);
            cp16(st + ATILE + so, Bh + (size_t)(bn + row)*K + kc + ch*8);
        }
        asm volatile("cp.async.commit_group;" ::: "memory");
    };

    const int NK = K >> 5;
    issue_loads(0, 0);
    issue_loads(1, 1);

    // per-lane ldmatrix row bases + swizzle keys
    const int khalf = lane >> 4;
    uint32_t baseA[4], baseB[4];
    uint32_t swA[4], swB[4];
    #pragma unroll
    for (int f = 0; f < 4; ++f) {
        const int rA = wm + (lane & 15) + f*16;
        const int rB = wn + (lane & 15) + f*16;
        baseA[f] = (uint32_t)rA * 64;  swA[f] = (uint32_t)((rA >> 1) & 3);
        baseB[f] = (uint32_t)rB * 64;  swB[f] = (uint32_t)((rB >> 1) & 3);
    }

    for (int c = 0; c < NK; ++c) {
        const int s = c & 1;
        if (c + 1 < NK) asm volatile("cp.async.wait_group 1;" ::: "memory");
        else            asm volatile("cp.async.wait_group 0;" ::: "memory");
        __syncthreads();
        const uint32_t st = tb + s*GSTG;

        #pragma unroll
        for (int ks = 0; ks < 2; ++ks) {
            const uint32_t lch = (uint32_t)(2*ks + khalf);
            uint32_t a[4][4], b4[4][4];
            #pragma unroll
            for (int mf = 0; mf < 4; ++mf)
                ldm_x4(a[mf], st + baseA[mf] + ((lch ^ swA[mf]) << 4));
            #pragma unroll
            for (int nb = 0; nb < 4; ++nb)
                ldm_x4(b4[nb], st + ATILE + baseB[nb] + ((lch ^ swB[nb]) << 4));
            #pragma unroll
            for (int mf = 0; mf < 4; ++mf)
                #pragma unroll
                for (int nb = 0; nb < 4; ++nb) {
                    uint32_t bb0[2] = { b4[nb][0], b4[nb][2] };
                    uint32_t bb1[2] = { b4[nb][1], b4[nb][3] };
                    mma16816(acc[mf][2*nb],   a[mf], bb0);
                    mma16816(acc[mf][2*nb+1], a[mf], bb1);
                }
        }
        __syncthreads();
        if (c + 2 < NK) issue_loads(c + 2, s);
    }

    // -------- epilogue: fragments direct to global ----------------------------
    const int qr = lane >> 2, qc = (lane & 3) * 2;
    #pragma unroll
    for (int mf = 0; mf < 4; ++mf) {
        #pragma unroll
        for (int half_ = 0; half_ < 2; ++half_) {
            const int r = bm + wm + mf*16 + qr + half_*8;
            #pragma unroll
            for (int nf = 0; nf < 8; ++nf) {
                const int n = bn + wn + nf*8 + qc;
                float c0 = acc[mf][nf][half_*2+0] + bias[n];
                float c1 = acc[mf][nf][half_*2+1] + bias[n+1];
                const size_t go = (size_t)r*N + n;
                if (MODE == 1) {
                    const float2 rr = *reinterpret_cast<const float2*>(&resid[go]);
                    c0 += rr.x; c1 += rr.y;
                    float2 o; o.x = c0; o.y = c1;
                    *reinterpret_cast<float2*>(&outF[go]) = o;
                } else if (MODE == 2) {
                    c0 = fmaxf(c0, 0.f); c1 = fmaxf(c1, 0.f);
                    *reinterpret_cast<uint32_t*>(outH + go) = pkh2(c0, c1);
                } else {
                    *reinterpret_cast<uint32_t*>(outH + go) = pkh2(c0, c1);
                }
            }
        }
    }
}

// ---------------- Flash attention (fp16, 128 q-rows/block, cp.async K/V) -------
// Block 256 thr (8 warps), 128 q-rows per block, 64-key tiles.
#define HPITCH 72                       // fp16 elements per smem row (144 B)
#define HPITCHB 144

__global__ __launch_bounds__(256)
void attn_h_kernel(const __half* __restrict__ qkvh, const int* __restrict__ seq_ls,
                   __half* __restrict__ yh)
{
    const int qt = blockIdx.x, h = blockIdx.y, b = blockIdx.z;

    __shared__ __align__(16) __half Qs[128*HPITCH];
    __shared__ __align__(16) __half Ks[64*HPITCH];
    __shared__ __align__(16) __half Vs[64*HPITCH];

    const int tid = threadIdx.x;
    const int wid = tid >> 5, lane = tid & 31;
    const int wm16 = wid * 16;
    const int seq_l = seq_ls[b];
    const int q0 = b*Tn + qt*128;
    const int kvoff = h*HDd;

    // Load Q tile (128 rows x 64 fp16; 16B vector copies)
    {
        const int r = tid >> 1, c0 = (tid & 1) * 32;
        const __half* src = qkvh + (size_t)(q0 + r)*3*Cn + kvoff + c0;
        __half* dst = Qs + r*HPITCH + c0;
        #pragma unroll
        for (int i = 0; i < 4; ++i)
            *reinterpret_cast<uint4*>(dst + i*8) =
                *reinterpret_cast<const uint4*>(src + i*8);
    }

    const uint32_t qs = smem_u32(Qs), ks_ = smem_u32(Ks), vs = smem_u32(Vs);
    const uint32_t a_r  = (uint32_t)(wm16 + (lane & 15)) * HPITCHB + (lane >> 4) * 16;
    const uint32_t bk_r = (uint32_t)(lane & 7) * HPITCHB + ((lane >> 3) & 1) * 16;
    const uint32_t bv_r = (uint32_t)(lane & 15) * HPITCHB;

    float m0 = -3.0e38f, m1 = -3.0e38f, l0 = 0.f, l1 = 0.f;
    float acc_o[8][4];
    #pragma unroll
    for (int nf = 0; nf < 8; ++nf)
        #pragma unroll
        for (int q = 0; q < 4; ++q) acc_o[nf][q] = 0.f;

    const int tc2 = (lane & 3) * 2;
    const int nkt = (seq_l + 63) >> 6;

    for (int kb = 0; kb < nkt; ++kb) {
        const int kbase = kb << 6;
        __syncthreads();
        // Load K,V tiles via cp.async (64 rows x 128B each; 2 units/thread/tile)
        {
            #pragma unroll
            for (int i = 0; i < 2; ++i) {
                const int u = tid + i*256;
                const int row = u >> 3, ch = u & 7;
                const uint32_t so = (uint32_t)(row*HPITCHB + ch*16);
                const size_t gb = (size_t)(b*Tn + kbase + row)*3*Cn + kvoff + ch*8;
                cp16(ks_ + so, qkvh + gb + Cn);
                cp16(vs  + so, qkvh + gb + 2*Cn);
            }
            asm volatile("cp.async.commit_group;" ::: "memory");
            asm volatile("cp.async.wait_group 0;" ::: "memory");
        }
        __syncthreads();

        // ---- S = Q K^T (128x64 per block; this warp: 16x64) ----
        float sacc[8][4];
        #pragma unroll
        for (int nf = 0; nf < 8; ++nf)
            #pragma unroll
            for (int q = 0; q < 4; ++q) sacc[nf][q] = 0.f;
        #pragma unroll
        for (int ksid = 0; ksid < 4; ++ksid) {
            uint32_t a[4];
            ldm_x4(a, qs + a_r + ksid*32);
            #pragma unroll
            for (int nf = 0; nf < 8; ++nf) {
                uint32_t bb[2];
                ldm_x2(bb, ks_ + bk_r + nf*8*HPITCHB + ksid*32);
                mma16816(sacc[nf], a, bb);
            }
        }

        // ---- scale (1/sqrt(64)) + mask invalid keys ----
        #pragma unroll
        for (int nf = 0; nf < 8; ++nf) {
            sacc[nf][0] *= 0.125f; sacc[nf][1] *= 0.125f;
            sacc[nf][2] *= 0.125f; sacc[nf][3] *= 0.125f;
            const int kc = kbase + nf*8 + tc2;
            if (kc     >= seq_l) { sacc[nf][0] = -1.0e30f; sacc[nf][2] = -1.0e30f; }
            if (kc + 1 >= seq_l) { sacc[nf][1] = -1.0e30f; sacc[nf][3] = -1.0e30f; }
        }

        // ---- online softmax (rows g=lane>>2 and g+8) ----
        float mx0 = -3.0e38f, mx1 = -3.0e38f;
        #pragma unroll
        for (int nf = 0; nf < 8; ++nf) {
            mx0 = fmaxf(mx0, fmaxf(sacc[nf][0], sacc[nf][1]));
            mx1 = fmaxf(mx1, fmaxf(sacc[nf][2], sacc[nf][3]));
        }
        mx0 = fmaxf(mx0, __shfl_xor_sync(0xffffffffu, mx0, 1));
        mx0 = fmaxf(mx0, __shfl_xor_sync(0xffffffffu, mx0, 2));
        mx1 = fmaxf(mx1, __shfl_xor_sync(0xffffffffu, mx1, 1));
        mx1 = fmaxf(mx1, __shfl_xor_sync(0xffffffffu, mx1, 2));
        const float mn0 = fmaxf(m0, mx0), mn1 = fmaxf(m1, mx1);
        const float f0 = __expf(m0 - mn0), f1 = __expf(m1 - mn1);
        float s0 = 0.f, s1 = 0.f;
        #pragma unroll
        for (int nf = 0; nf < 8; ++nf) {
            sacc[nf][0] = __expf(sacc[nf][0] - mn0);
            sacc[nf][1] = __expf(sacc[nf][1] - mn0);
            sacc[nf][2] = __expf(sacc[nf][2] - mn1);
            sacc[nf][3] = __expf(sacc[nf][3] - mn1);
            s0 += sacc[nf][0] + sacc[nf][1];
            s1 += sacc[nf][2] + sacc[nf][3];
        }
        s0 += __shfl_xor_sync(0xffffffffu, s0, 1);
        s0 += __shfl_xor_sync(0xffffffffu, s0, 2);
        s1 += __shfl_xor_sync(0xffffffffu, s1, 1);
        s1 += __shfl_xor_sync(0xffffffffu, s1, 2);
        m0 = mn0; m1 = mn1;
        l0 = l0*f0 + s0; l1 = l1*f1 + s1;
        #pragma unroll
        for (int nf = 0; nf < 8; ++nf) {
            acc_o[nf][0] *= f0; acc_o[nf][1] *= f0;
            acc_o[nf][2] *= f1; acc_o[nf][3] *= f1;
        }

        // ---- O += P @ V (P repacked from sacc; V via ldmatrix.trans) ----
        #pragma unroll
        for (int ksid = 0; ksid < 4; ++ksid) {
            uint32_t a[4];
            a[0] = pkh2(sacc[2*ksid  ][0], sacc[2*ksid  ][1]);
            a[1] = pkh2(sacc[2*ksid  ][2], sacc[2*ksid  ][3]);
            a[2] = pkh2(sacc[2*ksid+1][0], sacc[2*ksid+1][1]);
            a[3] = pkh2(sacc[2*ksid+1][2], sacc[2*ksid+1][3]);
            #pragma unroll
            for (int nf = 0; nf < 8; ++nf) {
                uint32_t bb[2];
                ldm_x2t(bb, vs + bv_r + ksid*16*HPITCHB + nf*16);
                mma16816(acc_o[nf], a, bb);
            }
        }
    }

    // ---- epilogue: O / l -> fp16 ----
    const float inv0 = 1.0f / l0, inv1 = 1.0f / l1;
    const int g = lane >> 2;
    #pragma unroll
    for (int nf = 0; nf < 8; ++nf) {
        const int col = kvoff + nf*8 + tc2;
        const size_t r0o = (size_t)(q0 + wm16 + g)*Cn + col;
        const size_t r1o = (size_t)(q0 + wm16 + g + 8)*Cn + col;
        *reinterpret_cast<uint32_t*>(yh + r0o) = pkh2(acc_o[nf][0]*inv0, acc_o[nf][1]*inv0);
        *reinterpret_cast<uint32_t*>(yh + r1o) = pkh2(acc_o[nf][2]*inv1, acc_o[nf][3]*inv1);
    }
}

// ---------------- launch ------------------------------------------------------
extern "C" void kernel_launch(void* const* d_in, const int* in_sizes, int n_in,
                              void* d_out, int out_size)
{
    const float* x      = (const float*)d_in[0];
    const int*   seq_ls = (const int*)  d_in[1];
    const float* ln1_g  = (const float*)d_in[2];
    const float* ln1_b  = (const float*)d_in[3];
    const float* w_qkv  = (const float*)d_in[4];
    const float* b_qkv  = (const float*)d_in[5];
    const float* w_proj = (const float*)d_in[6];
    const float* b_proj = (const float*)d_in[7];
    const float* ln2_g  = (const float*)d_in[8];
    const float* ln2_b  = (const float*)d_in[9];
    const float* w_fc   = (const float*)d_in[10];
    const float* b_fc   = (const float*)d_in[11];
    const float* w_fc2  = (const float*)d_in[12];
    const float* b_fc2  = (const float*)d_in[13];
    float* out = (float*)d_out;

    float *x1;
    __half *qkvh, *ah, *yh, *ffh, *wh;
    cudaGetSymbolAddress((void**)&qkvh, g_qkvh);
    cudaGetSymbolAddress((void**)&x1,   g_x1);
    cudaGetSymbolAddress((void**)&ah,   g_ah);
    cudaGetSymbolAddress((void**)&yh,   g_yh);
    cudaGetSymbolAddress((void**)&ffh,  g_ffh);
    cudaGetSymbolAddress((void**)&wh,   g_wh);

    // 0. transpose weights -> [N,K] fp16
    wt_h_kernel<<<dim3(3*Cn/32, Cn/32), 256>>>(w_qkv,  wh+OFF_QKV,  Cn,  3*Cn);
    wt_h_kernel<<<dim3(Cn/32,   Cn/32), 256>>>(w_proj, wh+OFF_PROJ, Cn,  Cn);
    wt_h_kernel<<<dim3(FFf/32,  Cn/32), 256>>>(w_fc,   wh+OFF_FC,   Cn,  FFf);
    wt_h_kernel<<<dim3(Cn/32,  FFf/32), 256>>>(w_fc2,  wh+OFF_FC2,  FFf, Cn);

    // 1. LN1 -> fp16
    ln_h_kernel<<<MROWS, 256>>>(x, ln1_g, ln1_b, ah);
    // 2. QKV projection -> fp16 qkv
    tc_gemm<0><<<dim3(3*Cn/128, MROWS/256), 256>>>(
        ah, wh+OFF_QKV, b_qkv, nullptr, nullptr, qkvh, MROWS, 3*Cn, Cn);
    // 3. Attention (fp16 tensor cores, 128-row q tiles) -> y fp16
    attn_h_kernel<<<dim3(Tn/128, NHh, Bn), 256>>>(qkvh, seq_ls, yh);
    // 4. proj + residual(x) -> x1 (fp32)
    tc_gemm<1><<<dim3(Cn/128, MROWS/256), 256>>>(
        yh, wh+OFF_PROJ, b_proj, x, x1, nullptr, MROWS, Cn, Cn);
    // 5. LN2 -> fp16
    ln_h_kernel<<<MROWS, 256>>>(x1, ln2_g, ln2_b, ah);
    // 6. FC + ReLU -> ff fp16
    tc_gemm<2><<<dim3(FFf/128, MROWS/256), 256>>>(
        ah, wh+OFF_FC, b_fc, nullptr, nullptr, ffh, MROWS, FFf, Cn);
    // 7. FC2 + residual(x1) -> out
    tc_gemm<1><<<dim3(Cn/128, MROWS/256), 256>>>(
        ffh, wh+OFF_FC2, b_fc2, x1, out, nullptr, MROWS, Cn, FFf);
}

// round 16
// speedup vs baseline: 1.1003x; 1.1003x over previous
#include <cuda_runtime.h>
#include <cuda_fp16.h>
#include <cstdint>
#include <math.h>

// Problem dims (fixed)
#define Bn 8
#define Tn 1024
#define Cn 1024
#define NHh 16
#define HDd 64
#define FFf 4096
#define MROWS (Bn*Tn)   // 8192

// Weight offsets inside the packed transposed-weight buffer (elements)
#define OFF_QKV 0
#define OFF_PROJ (3*Cn*Cn)
#define OFF_FC   (OFF_PROJ + Cn*Cn)
#define OFF_FC2  (OFF_FC + (size_t)FFf*Cn)
#define WSUM     (OFF_FC2 + (size_t)Cn*FFf)

// ---------------- scratch (static device globals; no allocation) -------------
static __device__ __align__(16) __half  g_qkvh[(size_t)MROWS*3*Cn]; // 48 MB
static __device__ __align__(16) float   g_x1 [(size_t)MROWS*Cn];    // 32 MB
static __device__ __align__(16) __half  g_ah [(size_t)MROWS*Cn];    // LN out fp16
static __device__ __align__(16) __half  g_yh [(size_t)MROWS*Cn];    // attn out fp16
static __device__ __align__(16) __half  g_ffh[(size_t)MROWS*FFf];   // relu(fc) fp16
static __device__ __align__(16) __half  g_wh [WSUM];                // W^T fp16

// ---------------- small helpers ------------------------------------------------
__device__ __forceinline__ uint32_t smem_u32(const void* p) {
    uint32_t a;
    asm("{ .reg .u64 t; cvta.to.shared.u64 t, %1; cvt.u32.u64 %0, t; }" : "=r"(a) : "l"(p));
    return a;
}
__device__ __forceinline__ void cp16(uint32_t dst, const void* src) {
    asm volatile("cp.async.cg.shared.global [%0], [%1], 16;" :: "r"(dst), "l"(src) : "memory");
}
__device__ __forceinline__ uint32_t pkh2(float a, float b) {
    __half2 t = __floats2half2_rn(a, b);
    return *reinterpret_cast<uint32_t*>(&t);
}
__device__ __forceinline__ void ldm_x4(uint32_t* r, uint32_t addr) {
    asm volatile("ldmatrix.sync.aligned.m8n8.x4.shared.b16 {%0,%1,%2,%3}, [%4];"
                 : "=r"(r[0]), "=r"(r[1]), "=r"(r[2]), "=r"(r[3]) : "r"(addr));
}
__device__ __forceinline__ void ldm_x2(uint32_t* r, uint32_t addr) {
    asm volatile("ldmatrix.sync.aligned.m8n8.x2.shared.b16 {%0,%1}, [%2];"
                 : "=r"(r[0]), "=r"(r[1]) : "r"(addr));
}
__device__ __forceinline__ void ldm_x2t(uint32_t* r, uint32_t addr) {
    asm volatile("ldmatrix.sync.aligned.m8n8.x2.trans.shared.b16 {%0,%1}, [%2];"
                 : "=r"(r[0]), "=r"(r[1]) : "r"(addr));
}
__device__ __forceinline__ void mma16816(float* c, const uint32_t* a, const uint32_t* b) {
    asm volatile(
        "mma.sync.aligned.m16n8k16.row.col.f32.f16.f16.f32 "
        "{%0,%1,%2,%3}, {%4,%5,%6,%7}, {%8,%9}, {%0,%1,%2,%3};"
        : "+f"(c[0]), "+f"(c[1]), "+f"(c[2]), "+f"(c[3])
        : "r"(a[0]), "r"(a[1]), "r"(a[2]), "r"(a[3]), "r"(b[0]), "r"(b[1]));
}

// ---------------- LayerNorm -> fp16 --------------------------------------------
__global__ __launch_bounds__(256)
void ln_h_kernel(const float* __restrict__ x, const float* __restrict__ gamma,
                 const float* __restrict__ beta, __half* __restrict__ oh)
{
    const int row = blockIdx.x;
    const float4* xr = reinterpret_cast<const float4*>(x + (size_t)row * Cn);
    float4 v = xr[threadIdx.x];
    float s  = v.x + v.y + v.z + v.w;
    float ss = v.x*v.x + v.y*v.y + v.z*v.z + v.w*v.w;
    #pragma unroll
    for (int o = 16; o > 0; o >>= 1) {
        s  += __shfl_xor_sync(0xffffffffu, s,  o);
        ss += __shfl_xor_sync(0xffffffffu, ss, o);
    }
    __shared__ float rs[8], rss[8];
    const int w = threadIdx.x >> 5;
    if ((threadIdx.x & 31) == 0) { rs[w] = s; rss[w] = ss; }
    __syncthreads();
    if (threadIdx.x < 32) {
        float ts  = (threadIdx.x < 8) ? rs[threadIdx.x]  : 0.f;
        float tss = (threadIdx.x < 8) ? rss[threadIdx.x] : 0.f;
        #pragma unroll
        for (int o = 4; o > 0; o >>= 1) {
            ts  += __shfl_xor_sync(0xffffffffu, ts,  o);
            tss += __shfl_xor_sync(0xffffffffu, tss, o);
        }
        if (threadIdx.x == 0) {
            float mean = ts * (1.0f/Cn);
            float var  = tss * (1.0f/Cn) - mean*mean;
            rs[0]  = mean;
            rss[0] = rsqrtf(var + 1e-5f);
        }
    }
    __syncthreads();
    const float mean = rs[0], rstd = rss[0];
    const float4 g4 = reinterpret_cast<const float4*>(gamma)[threadIdx.x];
    const float4 b4 = reinterpret_cast<const float4*>(beta )[threadIdx.x];
    uint2 h;
    h.x = pkh2((v.x - mean)*rstd*g4.x + b4.x, (v.y - mean)*rstd*g4.y + b4.y);
    h.y = pkh2((v.z - mean)*rstd*g4.z + b4.z, (v.w - mean)*rstd*g4.w + b4.w);
    *reinterpret_cast<uint2*>(oh + (size_t)row*Cn + threadIdx.x*4) = h;
}

// ---------------- weight transpose: W[K,N] -> Wt[N,K] fp16 ---------------------
__global__ __launch_bounds__(256)
void wt_h_kernel(const float* __restrict__ W, __half* __restrict__ wh, int K, int N)
{
    __shared__ float tile[32][33];
    const int n0 = blockIdx.x * 32, k0 = blockIdx.y * 32;
    const int tx = threadIdx.x & 31, ty = threadIdx.x >> 5;   // 32 x 8
    #pragma unroll
    for (int yy = ty; yy < 32; yy += 8)
        tile[yy][tx] = W[(size_t)(k0 + yy)*N + n0 + tx];
    __syncthreads();
    #pragma unroll
    for (int yy = ty; yy < 32; yy += 8)
        wh[(size_t)(n0 + yy)*K + k0 + tx] = __float2half_rn(tile[tx][yy]);
}

// ---------------- mma.sync fp16 GEMM (R13 config: 4 warps, 3-stage) ------------
// Block 128x128, BK=32, 4 warps (2x2), warp tile 64x64. 3 stages x 16KB = 48KB.
// Rows 64B; 16B chunk swizzle: phys = ch ^ ((row>>1)&3).
// MODE 0: outH = C+bias (fp16) ; MODE 1: outF = C+bias+resid (fp32) ;
// MODE 2: relu(C+bias) -> fp16
#define GTILE 8192                      // 128 rows * 64 B
#define GSTG  (2*GTILE)                 // A|B per stage = 16384 B

template<int MODE>
__global__ __launch_bounds__(128, 2)
void tc_gemm(const __half* __restrict__ Ah, const __half* __restrict__ Bh,
             const float* __restrict__ bias, const float* __restrict__ resid,
             float* __restrict__ outF, __half* __restrict__ outH,
             int M, int N, int K)
{
    __shared__ __align__(16) char smem[3*GSTG];   // 49152 B
    const uint32_t tb = smem_u32(smem);
    const int tid = threadIdx.x;
    const int wid = tid >> 5, lane = tid & 31;
    const int bm = blockIdx.y << 7, bn = blockIdx.x << 7;
    const int wm = (wid >> 1) * 64;
    const int wn = (wid & 1) * 64;

    float acc[4][8][4];
    #pragma unroll
    for (int i = 0; i < 4; ++i)
        #pragma unroll
        for (int j = 0; j < 8; ++j)
            #pragma unroll
            for (int q = 0; q < 4; ++q) acc[i][j][q] = 0.f;

    auto issue_loads = [&](int c, int s) {
        const uint32_t st = tb + s*GSTG;
        const int kc = c << 5;
        #pragma unroll
        for (int i = 0; i < 4; ++i) {
            const int u = tid + i*128;
            const int row = u >> 2, ch = u & 3;
            const uint32_t so = (uint32_t)(row*64 + ((ch ^ ((row>>1)&3)))*16);
            cp16(st +         so, Ah + (size_t)(bm + row)*K + kc + ch*8);
            cp16(st + GTILE + so, Bh + (size_t)(bn + row)*K + kc + ch*8);
        }
        asm volatile("cp.async.commit_group;" ::: "memory");
    };

    const int NK = K >> 5;
    issue_loads(0, 0);
    issue_loads(1, 1);

    const int khalf = lane >> 4;
    uint32_t baseA[4], baseB[4];
    uint32_t swA[4], swB[4];
    #pragma unroll
    for (int f = 0; f < 4; ++f) {
        const int rA = wm + (lane & 15) + f*16;
        const int rB = wn + (lane & 15) + f*16;
        baseA[f] = (uint32_t)rA * 64;  swA[f] = (uint32_t)((rA >> 1) & 3);
        baseB[f] = (uint32_t)rB * 64;  swB[f] = (uint32_t)((rB >> 1) & 3);
    }

    int s = 0;
    for (int c = 0; c < NK; ++c) {
        if (c + 1 < NK) asm volatile("cp.async.wait_group 1;" ::: "memory");
        else            asm volatile("cp.async.wait_group 0;" ::: "memory");
        __syncthreads();
        const uint32_t st = tb + s*GSTG;

        #pragma unroll
        for (int ks = 0; ks < 2; ++ks) {
            const uint32_t lch = (uint32_t)(2*ks + khalf);
            uint32_t a[4][4], b4[4][4];
            #pragma unroll
            for (int mf = 0; mf < 4; ++mf)
                ldm_x4(a[mf], st + baseA[mf] + ((lch ^ swA[mf]) << 4));
            #pragma unroll
            for (int nb = 0; nb < 4; ++nb)
                ldm_x4(b4[nb], st + GTILE + baseB[nb] + ((lch ^ swB[nb]) << 4));
            #pragma unroll
            for (int mf = 0; mf < 4; ++mf)
                #pragma unroll
                for (int nb = 0; nb < 4; ++nb) {
                    uint32_t bb0[2] = { b4[nb][0], b4[nb][2] };
                    uint32_t bb1[2] = { b4[nb][1], b4[nb][3] };
                    mma16816(acc[mf][2*nb],   a[mf], bb0);
                    mma16816(acc[mf][2*nb+1], a[mf], bb1);
                }
        }
        if (c + 2 < NK) {
            int s2 = s + 2; if (s2 >= 3) s2 -= 3;
            issue_loads(c + 2, s2);
        }
        if (++s == 3) s = 0;
    }

    const int qr = lane >> 2, qc = (lane & 3) * 2;
    #pragma unroll
    for (int mf = 0; mf < 4; ++mf) {
        #pragma unroll
        for (int half_ = 0; half_ < 2; ++half_) {
            const int r = bm + wm + mf*16 + qr + half_*8;
            #pragma unroll
            for (int nf = 0; nf < 8; ++nf) {
                const int n = bn + wn + nf*8 + qc;
                float c0 = acc[mf][nf][half_*2+0] + bias[n];
                float c1 = acc[mf][nf][half_*2+1] + bias[n+1];
                const size_t go = (size_t)r*N + n;
                if (MODE == 1) {
                    const float2 rr = *reinterpret_cast<const float2*>(&resid[go]);
                    c0 += rr.x; c1 += rr.y;
                    float2 o; o.x = c0; o.y = c1;
                    *reinterpret_cast<float2*>(&outF[go]) = o;
                } else if (MODE == 2) {
                    c0 = fmaxf(c0, 0.f); c1 = fmaxf(c1, 0.f);
                    *reinterpret_cast<uint32_t*>(outH + go) = pkh2(c0, c1);
                } else {
                    *reinterpret_cast<uint32_t*>(outH + go) = pkh2(c0, c1);
                }
            }
        }
    }
}

// ---------------- Flash attention (fp16, 128 q-rows, double-buffered K/V) ------
// Block 256 thr (8 warps), 128 q-rows per block, 64-key tiles.
// Rows 128B exact; 16B chunk swizzle: phys = ch ^ (row&7). Conflict-safe ldmatrix.
// Q 16KB + K 2x8KB + V 2x8KB = 48KB static.
#define AQOFF 0
#define AKOFF 16384
#define AVOFF 32768
#define AKVT  8192                      // one K or V stage = 64 rows * 128 B

__global__ __launch_bounds__(256)
void attn_h_kernel(const __half* __restrict__ qkvh, const int* __restrict__ seq_ls,
                   __half* __restrict__ yh)
{
    __shared__ __align__(16) char smem[49152];
    const uint32_t sb = smem_u32(smem);
    const int qt = blockIdx.x, h = blockIdx.y, b = blockIdx.z;

    const int tid = threadIdx.x;
    const int wid = tid >> 5, lane = tid & 31;
    const int wm16 = wid * 16;
    const int seq_l = seq_ls[b];
    const int q0 = b*Tn + qt*128;
    const int kvoff = h*HDd;
    const int nkt = (seq_l + 63) >> 6;

    // ---- Q load: 128 rows x 8 chunks = 1024 units, cp.async, group 0 ----
    #pragma unroll
    for (int i = 0; i < 4; ++i) {
        const int u = tid + i*256;
        const int row = u >> 3, ch = u & 7;
        const uint32_t so = (uint32_t)(row*128 + ((ch ^ (row&7)))*16);
        cp16(sb + AQOFF + so, qkvh + (size_t)(q0 + row)*3*Cn + kvoff + ch*8);
    }
    asm volatile("cp.async.commit_group;" ::: "memory");

    // ---- K/V stage loader: 64 rows x 8 chunks x 2 tiles; 2 units/thr/tile ----
    auto issue_kv = [&](int kb, int s) {
        const int kbase = kb << 6;
        #pragma unroll
        for (int i = 0; i < 2; ++i) {
            const int u = tid + i*256;
            const int row = u >> 3, ch = u & 7;
            const uint32_t so = (uint32_t)(s*AKVT + row*128 + ((ch ^ (row&7)))*16);
            const size_t gb = (size_t)(b*Tn + kbase + row)*3*Cn + kvoff + ch*8;
            cp16(sb + AKOFF + so, qkvh + gb + Cn);
            cp16(sb + AVOFF + so, qkvh + gb + 2*Cn);
        }
        asm volatile("cp.async.commit_group;" ::: "memory");
    };
    issue_kv(0, 0);
    if (nkt > 1) issue_kv(1, 1);

    float m0 = -3.0e38f, m1 = -3.0e38f, l0 = 0.f, l1 = 0.f;
    float acc_o[8][4];
    #pragma unroll
    for (int nf = 0; nf < 8; ++nf)
        #pragma unroll
        for (int q = 0; q < 4; ++q) acc_o[nf][q] = 0.f;

    const int tc2 = (lane & 3) * 2;
    // per-lane addressing: Q rows, K rows, V rows (logical; swizzle applied per use)
    const int rowQ  = wm16 + (lane & 15);
    const uint32_t qbase = (uint32_t)rowQ * 128, qsw = (uint32_t)(rowQ & 7);
    const int rowK0 = lane & 7;                    // + nf*8
    const int rowV0 = lane & 15;                   // + ksid*16
    const uint32_t kh2 = (uint32_t)((lane >> 3) & 1);

    for (int kb = 0; kb < nkt; ++kb) {
        const int kbase = kb << 6;
        const int s = kb & 1;
        if (kb + 1 < nkt) asm volatile("cp.async.wait_group 1;" ::: "memory");
        else              asm volatile("cp.async.wait_group 0;" ::: "memory");
        __syncthreads();
        const uint32_t ks_s = sb + AKOFF + s*AKVT;
        const uint32_t vs_s = sb + AVOFF + s*AKVT;

        // ---- S = Q K^T (this warp: 16x64) ----
        float sacc[8][4];
        #pragma unroll
        for (int nf = 0; nf < 8; ++nf)
            #pragma unroll
            for (int q = 0; q < 4; ++q) sacc[nf][q] = 0.f;
        #pragma unroll
        for (int ksid = 0; ksid < 4; ++ksid) {
            const uint32_t lchA = (uint32_t)(2*ksid) + (uint32_t)(lane >> 4);
            uint32_t a[4];
            ldm_x4(a, sb + AQOFF + qbase + ((lchA ^ qsw) << 4));
            const uint32_t lchK = (uint32_t)(2*ksid) + kh2;
            #pragma unroll
            for (int nf = 0; nf < 8; ++nf) {
                const int rK = rowK0 + nf*8;
                uint32_t bb[2];
                ldm_x2(bb, ks_s + (uint32_t)rK*128 + ((lchK ^ (uint32_t)(rK & 7)) << 4));
                mma16816(sacc[nf], a, bb);
            }
        }

        // ---- scale (1/sqrt(64)) + mask invalid keys ----
        #pragma unroll
        for (int nf = 0; nf < 8; ++nf) {
            sacc[nf][0] *= 0.125f; sacc[nf][1] *= 0.125f;
            sacc[nf][2] *= 0.125f; sacc[nf][3] *= 0.125f;
            const int kc = kbase + nf*8 + tc2;
            if (kc     >= seq_l) { sacc[nf][0] = -1.0e30f; sacc[nf][2] = -1.0e30f; }
            if (kc + 1 >= seq_l) { sacc[nf][1] = -1.0e30f; sacc[nf][3] = -1.0e30f; }
        }

        // ---- online softmax (rows g=lane>>2 and g+8) ----
        float mx0 = -3.0e38f, mx1 = -3.0e38f;
        #pragma unroll
        for (int nf = 0; nf < 8; ++nf) {
            mx0 = fmaxf(mx0, fmaxf(sacc[nf][0], sacc[nf][1]));
            mx1 = fmaxf(mx1, fmaxf(sacc[nf][2], sacc[nf][3]));
        }
        mx0 = fmaxf(mx0, __shfl_xor_sync(0xffffffffu, mx0, 1));
        mx0 = fmaxf(mx0, __shfl_xor_sync(0xffffffffu, mx0, 2));
        mx1 = fmaxf(mx1, __shfl_xor_sync(0xffffffffu, mx1, 1));
        mx1 = fmaxf(mx1, __shfl_xor_sync(0xffffffffu, mx1, 2));
        const float mn0 = fmaxf(m0, mx0), mn1 = fmaxf(m1, mx1);
        const float f0 = __expf(m0 - mn0), f1 = __expf(m1 - mn1);
        float s0 = 0.f, s1 = 0.f;
        #pragma unroll
        for (int nf = 0; nf < 8; ++nf) {
            sacc[nf][0] = __expf(sacc[nf][0] - mn0);
            sacc[nf][1] = __expf(sacc[nf][1] - mn0);
            sacc[nf][2] = __expf(sacc[nf][2] - mn1);
            sacc[nf][3] = __expf(sacc[nf][3] - mn1);
            s0 += sacc[nf][0] + sacc[nf][1];
            s1 += sacc[nf][2] + sacc[nf][3];
        }
        s0 += __shfl_xor_sync(0xffffffffu, s0, 1);
        s0 += __shfl_xor_sync(0xffffffffu, s0, 2);
        s1 += __shfl_xor_sync(0xffffffffu, s1, 1);
        s1 += __shfl_xor_sync(0xffffffffu, s1, 2);
        m0 = mn0; m1 = mn1;
        l0 = l0*f0 + s0; l1 = l1*f1 + s1;
        #pragma unroll
        for (int nf = 0; nf < 8; ++nf) {
            acc_o[nf][0] *= f0; acc_o[nf][1] *= f0;
            acc_o[nf][2] *= f1; acc_o[nf][3] *= f1;
        }

        // ---- O += P @ V (P repacked from sacc; V via ldmatrix.trans) ----
        #pragma unroll
        for (int ksid = 0; ksid < 4; ++ksid) {
            uint32_t a[4];
            a[0] = pkh2(sacc[2*ksid  ][0], sacc[2*ksid  ][1]);
            a[1] = pkh2(sacc[2*ksid  ][2], sacc[2*ksid  ][3]);
            a[2] = pkh2(sacc[2*ksid+1][0], sacc[2*ksid+1][1]);
            a[3] = pkh2(sacc[2*ksid+1][2], sacc[2*ksid+1][3]);
            const int rV = rowV0 + ksid*16;
            #pragma unroll
            for (int nf = 0; nf < 8; ++nf) {
                uint32_t bb[2];
                ldm_x2t(bb, vs_s + (uint32_t)rV*128 +
                            (((uint32_t)nf ^ (uint32_t)(rV & 7)) << 4));
                mma16816(acc_o[nf], a, bb);
            }
        }
        __syncthreads();
        if (kb + 2 < nkt) issue_kv(kb + 2, s);
    }

    // ---- epilogue: O / l -> fp16 ----
    const float inv0 = 1.0f / l0, inv1 = 1.0f / l1;
    const int g = lane >> 2;
    #pragma unroll
    for (int nf = 0; nf < 8; ++nf) {
        const int col = kvoff + nf*8 + tc2;
        const size_t r0o = (size_t)(q0 + wm16 + g)*Cn + col;
        const size_t r1o = (size_t)(q0 + wm16 + g + 8)*Cn + col;
        *reinterpret_cast<uint32_t*>(yh + r0o) = pkh2(acc_o[nf][0]*inv0, acc_o[nf][1]*inv0);
        *reinterpret_cast<uint32_t*>(yh + r1o) = pkh2(acc_o[nf][2]*inv1, acc_o[nf][3]*inv1);
    }
}

// ---------------- launch ------------------------------------------------------
extern "C" void kernel_launch(void* const* d_in, const int* in_sizes, int n_in,
                              void* d_out, int out_size)
{
    const float* x      = (const float*)d_in[0];
    const int*   seq_ls = (const int*)  d_in[1];
    const float* ln1_g  = (const float*)d_in[2];
    const float* ln1_b  = (const float*)d_in[3];
    const float* w_qkv  = (const float*)d_in[4];
    const float* b_qkv  = (const float*)d_in[5];
    const float* w_proj = (const float*)d_in[6];
    const float* b_proj = (const float*)d_in[7];
    const float* ln2_g  = (const float*)d_in[8];
    const float* ln2_b  = (const float*)d_in[9];
    const float* w_fc   = (const float*)d_in[10];
    const float* b_fc   = (const float*)d_in[11];
    const float* w_fc2  = (const float*)d_in[12];
    const float* b_fc2  = (const float*)d_in[13];
    float* out = (float*)d_out;

    float *x1;
    __half *qkvh, *ah, *yh, *ffh, *wh;
    cudaGetSymbolAddress((void**)&qkvh, g_qkvh);
    cudaGetSymbolAddress((void**)&x1,   g_x1);
    cudaGetSymbolAddress((void**)&ah,   g_ah);
    cudaGetSymbolAddress((void**)&yh,   g_yh);
    cudaGetSymbolAddress((void**)&ffh,  g_ffh);
    cudaGetSymbolAddress((void**)&wh,   g_wh);

    // 0. transpose weights -> [N,K] fp16
    wt_h_kernel<<<dim3(3*Cn/32, Cn/32), 256>>>(w_qkv,  wh+OFF_QKV,  Cn,  3*Cn);
    wt_h_kernel<<<dim3(Cn/32,   Cn/32), 256>>>(w_proj, wh+OFF_PROJ, Cn,  Cn);
    wt_h_kernel<<<dim3(FFf/32,  Cn/32), 256>>>(w_fc,   wh+OFF_FC,   Cn,  FFf);
    wt_h_kernel<<<dim3(Cn/32,  FFf/32), 256>>>(w_fc2,  wh+OFF_FC2,  FFf, Cn);

    // 1. LN1 -> fp16
    ln_h_kernel<<<MROWS, 256>>>(x, ln1_g, ln1_b, ah);
    // 2. QKV projection -> fp16 qkv
    tc_gemm<0><<<dim3(3*Cn/128, MROWS/128), 128>>>(
        ah, wh+OFF_QKV, b_qkv, nullptr, nullptr, qkvh, MROWS, 3*Cn, Cn);
    // 3. Attention (fp16 tensor cores, 128-row q tiles) -> y fp16
    attn_h_kernel<<<dim3(Tn/128, NHh, Bn), 256>>>(qkvh, seq_ls, yh);
    // 4. proj + residual(x) -> x1 (fp32)
    tc_gemm<1><<<dim3(Cn/128, MROWS/128), 128>>>(
        yh, wh+OFF_PROJ, b_proj, x, x1, nullptr, MROWS, Cn, Cn);
    // 5. LN2 -> fp16
    ln_h_kernel<<<MROWS, 256>>>(x1, ln2_g, ln2_b, ah);
    // 6. FC + ReLU -> ff fp16
    tc_gemm<2><<<dim3(FFf/128, MROWS/128), 128>>>(
        ah, wh+OFF_FC, b_fc, nullptr, nullptr, ffh, MROWS, FFf, Cn);
    // 7. FC2 + residual(x1) -> out
    tc_gemm<1><<<dim3(Cn/128, MROWS/128), 128>>>(
        ffh, wh+OFF_FC2, b_fc2, x1, out, nullptr, MROWS, Cn, FFf);
}